// round 13
// baseline (speedup 1.0000x reference)
#include <cuda_runtime.h>
#include <math.h>

// Problem constants (FrameReducer: N=16, T=2048, C=512, V=500)
#define PN 16
#define PT 2048
#define PC 512
#define PV 500
#define RPB 8          // rows per gather block
#define MLP 4          // independent load-store pairs per thread

// Scratch (device globals; no allocation allowed)
__device__ int g_off[PN * PT];   // per OUTPUT row: source offset n*PT+t, or -1
__device__ int g_lens[PN];       // lens_fr per batch row

// threshold: float32(log(0.9)) — matches jnp float32 weak-typed comparison
#define LOG09 (-0.10536051565782628f)

// ---------------------------------------------------------------------------
// Robust x_lens read: JAX with x64 disabled dumps int32 despite astype(int64).
// Detect dtype from the first 64 bytes only (always in-bounds):
//   int64 layout: words[1,3,...,15] are high words of values in [1,2048] -> 0
//   int32 layout: words[1,3,...,15] are lens[1],lens[3],... in [1,2048] -> !=0
// ---------------------------------------------------------------------------
__device__ __forceinline__ long long read_xlen(const void* p, int n) {
    const int* w = (const int*)p;
    bool is64 = true;
#pragma unroll
    for (int i = 1; i < 16; i += 2) {
        if (w[i] != 0) { is64 = false; break; }
    }
    if (is64) return ((const long long*)p)[n];
    return (long long)w[n];
}

// Issue-only L2 prefetch of one 2KB x row (16 x 128B lines).
__device__ __forceinline__ void l2_prefetch_row(const float* base) {
    unsigned long long a = (unsigned long long)base;
#pragma unroll
    for (int i = 0; i < 16; i++) {
        asm volatile("prefetch.global.L2 [%0];" :: "l"(a + (unsigned)(i * 128)));
    }
}

// ---------------------------------------------------------------------------
// Kernel 1: per-row mask + stable compaction scan.
// One block per n, 1024 threads, 2 t-positions per thread (MLP=2).
// Emits the DENSE per-output-row offset table g_off[n*t_prime + r]:
//   r <  lens -> n*PT + t ; r >= lens -> -1 (zero row).
// Epilogue: issues L2 prefetches for every kept x row (issue-only, no data
// dependency) so the gather kernel's reads hit L2 instead of DRAM.
// Also writes the lens tail (2nd output).
// ---------------------------------------------------------------------------
__global__ void __launch_bounds__(1024)
mask_scan_kernel(const float* __restrict__ x,
                 const float* __restrict__ ctc,
                 const void* __restrict__ x_lens,
                 const int* __restrict__ blank_ptr,
                 float* __restrict__ out,
                 int t_prime, int rem) {
    const int n    = blockIdx.x;
    const int tid  = threadIdx.x;
    const int warp = tid >> 5;                 // 0..31
    const int lane = tid & 31;
    const int blank = blank_ptr ? blank_ptr[0] : 0;
    const long long xl = read_xlen(x_lens, n);

    const int t0 = warp * 64 + lane;
    const int t1 = t0 + 32;

    bool k0 = false, k1 = false;
    if ((long long)t0 < xl)
        k0 = (__ldcs(&ctc[((size_t)n * PT + t0) * PV + blank]) < LOG09);
    if ((long long)t1 < xl)
        k1 = (__ldcs(&ctc[((size_t)n * PT + t1) * PV + blank]) < LOG09);

    const unsigned b0 = __ballot_sync(0xffffffffu, k0);
    const unsigned b1 = __ballot_sync(0xffffffffu, k1);
    const int cnt = __popc(b0) + __popc(b1);

    __shared__ int wcnt[32];
    __shared__ int wbase[33];                  // [32] exclusive bases, [32]=total
    if (lane == 0) wcnt[warp] = cnt;
    __syncthreads();

    if (warp == 0) {                           // warp 0 scans the 32 warp counts
        const int v = wcnt[lane];
        int incl = v;
#pragma unroll
        for (int off = 1; off < 32; off <<= 1) {
            int u = __shfl_up_sync(0xffffffffu, incl, off);
            if (lane >= off) incl += u;
        }
        wbase[lane] = incl - v;
        if (lane == 31) wbase[32] = incl;      // row total = lens_fr[n]
    }
    __syncthreads();

    const int row_base = n * t_prime;
    const unsigned lt = (1u << lane) - 1u;
    const int base0 = wbase[warp];
    const int base1 = base0 + __popc(b0);
    if (k0) {
        const int r = base0 + __popc(b0 & lt);
        if (r < t_prime) g_off[row_base + r] = n * PT + t0;
    }
    if (k1) {
        const int r = base1 + __popc(b1 & lt);
        if (r < t_prime) g_off[row_base + r] = n * PT + t1;
    }

    const int total = wbase[32];
    // pad rows [total, t_prime) -> -1
    for (int r = total + tid; r < t_prime; r += 1024) {
        g_off[row_base + r] = -1;
    }

    // L2 prefetch of kept x rows (from register state; no readback chain)
    if (k0) l2_prefetch_row(x + ((size_t)n * PT + t0) * PC);
    if (k1) l2_prefetch_row(x + ((size_t)n * PT + t1) * PC);

    if (tid == 0) {
        g_lens[n] = total;
        if (rem > 0) {                         // lens tail (second output)
            const size_t off = (size_t)PN * t_prime * PC;
            if (rem == PN) {
                out[off + n] = (float)total;
            } else if (rem == 2 * PN) {
                reinterpret_cast<long long*>(out + off)[n] = (long long)total;
            }
        }
    }
}

// ---------------------------------------------------------------------------
// Kernel 2: gather/zero-fill. 8 rows per 256-thread block (R9 best config).
// Output is row-major in the flat row index: no div/mod anywhere.
// Prologue is ONE coalesced load of 8 consecutive g_off ints (L2-hot,
// no dependent chain), then each thread does 4 INDEPENDENT float4
// load->store pairs (front-batched, MLP=4). Reads should now be L2 hits
// thanks to the prefetch epilogue in kernel 1. Every output element
// written exactly once (d_out is poisoned).
// ---------------------------------------------------------------------------
__global__ void __launch_bounds__(256)
gather_kernel(const float* __restrict__ x,
              float* __restrict__ out,
              int total_rows) {
    __shared__ int s_off[RPB];

    const int row0 = blockIdx.x * RPB;
    const int tid  = threadIdx.x;

    if (tid < RPB) {
        const int row = row0 + tid;
        s_off[tid] = (row < total_rows) ? __ldcg(&g_off[row]) : -1;
    }
    __syncthreads();

    const int lane = tid & 127;                // float4 lane within a row
    const int half = tid >> 7;                 // 0 or 1

    int    offs[MLP];
    float4 vals[MLP];
#pragma unroll
    for (int i = 0; i < MLP; i++) {
        offs[i] = s_off[half + 2 * i];         // rows half, half+2, half+4, half+6
    }
#pragma unroll
    for (int i = 0; i < MLP; i++) {            // 4 independent loads, batched
        vals[i] = make_float4(0.f, 0.f, 0.f, 0.f);
        if (offs[i] >= 0) {
            vals[i] = __ldcs(reinterpret_cast<const float4*>(
                          x + (size_t)offs[i] * PC) + lane);
        }
    }
#pragma unroll
    for (int i = 0; i < MLP; i++) {
        const int row = row0 + half + 2 * i;
        if (row < total_rows) {
            reinterpret_cast<float4*>(out + (size_t)row * PC)[lane] = vals[i];
        }
    }
}

// ---------------------------------------------------------------------------
extern "C" void kernel_launch(void* const* d_in, const int* in_sizes, int n_in,
                              void* d_out, int out_size) {
    const float* x      = (const float*)d_in[0];    // [N,T,C] f32
    const void*  x_lens = d_in[1];                  // [N] i32 or i64 (detected)
    const float* ctc    = (const float*)d_in[2];    // [N,T,V] f32
    const int*   blank  = (n_in >= 4) ? (const int*)d_in[3] : nullptr;
    float*       out    = (float*)d_out;

    // T' is fixed by the harness via out_size: out_size = N*T'*C (+ lens tail)
    const int row = PN * PC;                 // 8192
    int t_prime = out_size / row;
    int rem = out_size - t_prime * row;
    if (t_prime < 1) t_prime = 1;

    const int total_rows = PN * t_prime;
    const int nblk = (total_rows + RPB - 1) / RPB;

    mask_scan_kernel<<<PN, 1024>>>(x, ctc, x_lens, blank, out, t_prime, rem);
    gather_kernel<<<nblk, 256>>>(x, out, total_rows);
}

// round 14
// speedup vs baseline: 1.6304x; 1.6304x over previous
#include <cuda_runtime.h>
#include <math.h>

// Problem constants (FrameReducer: N=16, T=2048, C=512, V=500)
#define PN 16
#define PT 2048
#define PC 512
#define PV 500
#define WPB 16         // warps (= rows) per gather block

// Scratch (device globals; no allocation allowed)
__device__ int g_off[PN * PT];   // per OUTPUT row: source offset n*PT+t, or -1
__device__ int g_lens[PN];       // lens_fr per batch row

// threshold: float32(log(0.9)) — matches jnp float32 weak-typed comparison
#define LOG09 (-0.10536051565782628f)

// ---------------------------------------------------------------------------
// Robust x_lens read: JAX with x64 disabled dumps int32 despite astype(int64).
// Detect dtype from the first 64 bytes only (always in-bounds):
//   int64 layout: words[1,3,...,15] are high words of values in [1,2048] -> 0
//   int32 layout: words[1,3,...,15] are lens[1],lens[3],... in [1,2048] -> !=0
// ---------------------------------------------------------------------------
__device__ __forceinline__ long long read_xlen(const void* p, int n) {
    const int* w = (const int*)p;
    bool is64 = true;
#pragma unroll
    for (int i = 1; i < 16; i += 2) {
        if (w[i] != 0) { is64 = false; break; }
    }
    if (is64) return ((const long long*)p)[n];
    return (long long)w[n];
}

// ---------------------------------------------------------------------------
// Kernel 1: per-row mask + stable compaction scan (R9 version, no prefetch).
// One block per n, 1024 threads, 2 t-positions per thread (MLP=2).
// Emits the DENSE per-output-row offset table g_off[n*t_prime + r]:
//   r <  lens -> n*PT + t ; r >= lens -> -1 (zero row).
// Also writes the lens tail (2nd output).
// ---------------------------------------------------------------------------
__global__ void __launch_bounds__(1024)
mask_scan_kernel(const float* __restrict__ ctc,
                 const void* __restrict__ x_lens,
                 const int* __restrict__ blank_ptr,
                 float* __restrict__ out,
                 int t_prime, int rem) {
    const int n    = blockIdx.x;
    const int tid  = threadIdx.x;
    const int warp = tid >> 5;                 // 0..31
    const int lane = tid & 31;
    const int blank = blank_ptr ? blank_ptr[0] : 0;
    const long long xl = read_xlen(x_lens, n);

    const int t0 = warp * 64 + lane;
    const int t1 = t0 + 32;

    bool k0 = false, k1 = false;
    if ((long long)t0 < xl)
        k0 = (__ldcs(&ctc[((size_t)n * PT + t0) * PV + blank]) < LOG09);
    if ((long long)t1 < xl)
        k1 = (__ldcs(&ctc[((size_t)n * PT + t1) * PV + blank]) < LOG09);

    const unsigned b0 = __ballot_sync(0xffffffffu, k0);
    const unsigned b1 = __ballot_sync(0xffffffffu, k1);
    const int cnt = __popc(b0) + __popc(b1);

    __shared__ int wcnt[32];
    __shared__ int wbase[33];                  // [32] exclusive bases, [32]=total
    if (lane == 0) wcnt[warp] = cnt;
    __syncthreads();

    if (warp == 0) {                           // warp 0 scans the 32 warp counts
        const int v = wcnt[lane];
        int incl = v;
#pragma unroll
        for (int off = 1; off < 32; off <<= 1) {
            int u = __shfl_up_sync(0xffffffffu, incl, off);
            if (lane >= off) incl += u;
        }
        wbase[lane] = incl - v;
        if (lane == 31) wbase[32] = incl;      // row total = lens_fr[n]
    }
    __syncthreads();

    const int row_base = n * t_prime;
    const unsigned lt = (1u << lane) - 1u;
    const int base0 = wbase[warp];
    const int base1 = base0 + __popc(b0);
    if (k0) {
        const int r = base0 + __popc(b0 & lt);
        if (r < t_prime) g_off[row_base + r] = n * PT + t0;
    }
    if (k1) {
        const int r = base1 + __popc(b1 & lt);
        if (r < t_prime) g_off[row_base + r] = n * PT + t1;
    }

    const int total = wbase[32];
    // pad rows [total, t_prime) -> -1
    for (int r = total + tid; r < t_prime; r += 1024) {
        g_off[row_base + r] = -1;
    }

    if (tid == 0) {
        g_lens[n] = total;
        if (rem > 0) {                         // lens tail (second output)
            const size_t off = (size_t)PN * t_prime * PC;
            if (rem == PN) {
                out[off + n] = (float)total;
            } else if (rem == 2 * PN) {
                reinterpret_cast<long long*>(out + off)[n] = (long long)total;
            }
        }
    }
}

// ---------------------------------------------------------------------------
// Kernel 2: gather/zero-fill. ONE WARP PER OUTPUT ROW. No shared memory,
// no __syncthreads — warps are fully independent, so a slow offset load
// for one row never stalls the other rows in the block.
// Per warp: 1 broadcast g_off load (1 sector, L2-hot) -> 4 independent
// coalesced LDG.128 covering the 2KB row (4 x 512B) -> 4 STG.128.
// Output is row-major in the flat row index: no div/mod. __ldcs: one-touch.
// Every output element written exactly once (d_out is poisoned).
// ---------------------------------------------------------------------------
__global__ void __launch_bounds__(512)
gather_kernel(const float* __restrict__ x,
              float* __restrict__ out,
              int total_rows) {
    const int wid  = threadIdx.x >> 5;         // 0..15: row within block
    const int lane = threadIdx.x & 31;
    const int row  = blockIdx.x * WPB + wid;
    if (row >= total_rows) return;

    const int off = __ldcg(&g_off[row]);       // warp-uniform broadcast load

    float4 v[4];
    if (off >= 0) {
        const float4* src = reinterpret_cast<const float4*>(
                                x + (size_t)off * PC);
#pragma unroll
        for (int k = 0; k < 4; k++) {          // 4 independent 512B warp-loads
            v[k] = __ldcs(src + lane + 32 * k);
        }
    } else {
#pragma unroll
        for (int k = 0; k < 4; k++) {
            v[k] = make_float4(0.f, 0.f, 0.f, 0.f);
        }
    }

    float4* dst = reinterpret_cast<float4*>(out + (size_t)row * PC);
#pragma unroll
    for (int k = 0; k < 4; k++) {
        dst[lane + 32 * k] = v[k];
    }
}

// ---------------------------------------------------------------------------
extern "C" void kernel_launch(void* const* d_in, const int* in_sizes, int n_in,
                              void* d_out, int out_size) {
    const float* x      = (const float*)d_in[0];    // [N,T,C] f32
    const void*  x_lens = d_in[1];                  // [N] i32 or i64 (detected)
    const float* ctc    = (const float*)d_in[2];    // [N,T,V] f32
    const int*   blank  = (n_in >= 4) ? (const int*)d_in[3] : nullptr;
    float*       out    = (float*)d_out;

    // T' is fixed by the harness via out_size: out_size = N*T'*C (+ lens tail)
    const int row = PN * PC;                 // 8192
    int t_prime = out_size / row;
    int rem = out_size - t_prime * row;
    if (t_prime < 1) t_prime = 1;

    const int total_rows = PN * t_prime;
    const int nblk = (total_rows + WPB - 1) / WPB;

    mask_scan_kernel<<<PN, 1024>>>(ctc, x_lens, blank, out, t_prime, rem);
    gather_kernel<<<nblk, 512>>>(x, out, total_rows);
}